// round 13
// baseline (speedup 1.0000x reference)
#include <cuda_runtime.h>
#include <cuda_bf16.h>
#include <stdint.h>

#define CH 256
#define NPIX 8525
#define NSLICE 72

// ---- scratch (bf16 hi/lo operand storage) ---------------------------------
__device__ __align__(16) __nv_bfloat16 g_wTh[2][4][NSLICE][256][32];
__device__ __align__(16) __nv_bfloat16 g_wTl[2][4][NSLICE][256][32];
__device__ __align__(16) __nv_bfloat16 g_wSh[NSLICE][128][32];   // 80 used
__device__ __align__(16) __nv_bfloat16 g_wSl[NSLICE][128][32];
__device__ __align__(16) __nv_bfloat16 g_wPh[NSLICE][8][32];     // pred4+iou1+pad
__device__ __align__(16) __nv_bfloat16 g_wPl[NSLICE][8][32];
__device__ __align__(16) __nv_bfloat16 g_featH[NPIX * CH];
__device__ __align__(16) __nv_bfloat16 g_featL[NPIX * CH];
__device__ __align__(16) __nv_bfloat16 g_actH[2][NPIX * CH];
__device__ __align__(16) __nv_bfloat16 g_actL[2][NPIX * CH];
__device__ float g_rawD[2][NPIX * CH];        // pre-GN fp32 [pix][ch]
__device__ float g_gsum[4][2][5][32][2];      // [step][tower][lvl][group]{s,ss}

__constant__ int   c_Hc[5]   = {80, 40, 20, 10, 5};
__constant__ int   c_HWc[5]  = {6400, 1600, 400, 100, 25};
__constant__ int   c_cum[5]  = {0, 6400, 8000, 8400, 8500};
__constant__ int   c_tcum[5] = {50, 63, 67, 68, 69};
__constant__ float c_strF[5] = {8.f, 16.f, 32.f, 64.f, 128.f};

#define MMAB(c, a, b0v, b1v) \
    asm volatile("mma.sync.aligned.m16n8k16.row.col.f32.bf16.bf16.f32 " \
        "{%0,%1,%2,%3},{%4,%5,%6,%7},{%8,%9},{%0,%1,%2,%3};" \
        : "+f"((c)[0]), "+f"((c)[1]), "+f"((c)[2]), "+f"((c)[3]) \
        : "r"((a)[0]), "r"((a)[1]), "r"((a)[2]), "r"((a)[3]), \
          "r"(b0v), "r"(b1v))

#define LDSM4(r, a) \
    asm volatile("ldmatrix.sync.aligned.m8n8.x4.shared.b16 {%0,%1,%2,%3}, [%4];" \
        : "=r"((r)[0]), "=r"((r)[1]), "=r"((r)[2]), "=r"((r)[3]) : "r"(a))

#define CP_COMMIT() asm volatile("cp.async.commit_group;" ::: "memory")
#define CP_WAIT(n)  asm volatile("cp.async.wait_group %0;" :: "n"(n) : "memory")

__device__ __forceinline__ void cp16(uint32_t dst, const void* src, bool ok) {
    asm volatile("cp.async.cg.shared.global [%0], [%1], 16, %2;"
                 :: "r"(dst), "l"(src), "r"(ok ? 16 : 0) : "memory");
}

// ---- SMEM layout (u32 units): pitch 20 u32/row ----------------------------
#define PITCH 20
#define OFF_AH 0
#define OFF_AL 2560
#define OFF_BH 5120
#define OFF_BL 7680
#define BUF_U32 10240
#define SMEM_BYTES (2 * BUF_U32 * 4)   // 81920
#define PREP_SMEM (8 * 2304 * 4)       // 73728

__device__ __forceinline__ uint32_t smem_addr_of(const void* p) {
    uint32_t a;
    asm("{ .reg .u64 t; cvta.to.shared.u64 t, %1; cvt.u32.u64 %0, t; }" : "=r"(a) : "l"(p));
    return a;
}
__device__ __forceinline__ int lvl_of_tile(int bx) {
    int l = 0;
    if (bx >= c_tcum[0]) l = 1;
    if (bx >= c_tcum[1]) l = 2;
    if (bx >= c_tcum[2]) l = 3;
    if (bx >= c_tcum[3]) l = 4;
    return l;
}
__device__ __forceinline__ int lvl_of_pix(int p) {
    int l = 0;
    if (p >= 6400) l = 1;
    if (p >= 8000) l = 2;
    if (p >= 8400) l = 3;
    if (p >= 8500) l = 4;
    return l;
}
__device__ __forceinline__ void bf_split(float v, __nv_bfloat16& h, __nv_bfloat16& lo) {
    h = __float2bfloat16_rn(v);
    lo = __float2bfloat16_rn(v - __bfloat162float(h));
}

// ---------------------------------------------------------------------------
// Async fill of one stage (bufAddr = SMEM byte addr of stage base)
// ---------------------------------------------------------------------------
template <int WROWS, int BROWS_DATA, int BROWS_PAD>
__device__ __forceinline__ void fill_async(
    uint32_t bufAddr, int s,
    const __nv_bfloat16* __restrict__ ihh, const __nv_bfloat16* __restrict__ ill,
    const __nv_bfloat16* __restrict__ wh, const __nv_bfloat16* __restrict__ wl,
    int ocr0, const int* ah, const int* aw, const bool* apv, int H, int W)
{
    const int tid = threadIdx.x;
    const int rs = s >> 3, ic0 = (s & 7) * 32;
    const int dr = rs / 3 - 1, ds = rs % 3 - 1;

#pragma unroll
    for (int it = 0; it < 4; it++) {
        int slot = tid + it * 256;
        int hilo = slot >> 9, rowp = (slot >> 2) & 127, c8 = slot & 3;
        int hh = ah[it] + dr, ww = aw[it] + ds;
        bool ok = apv[it] && (unsigned)hh < (unsigned)H && (unsigned)ww < (unsigned)W;
        const __nv_bfloat16* src = (hilo ? ill : ihh) +
            (ok ? ((size_t)(hh * W + ww) * 256 + ic0 + c8 * 8) : 0);
        uint32_t dst = bufAddr +
            (((hilo ? OFF_AL : OFF_AH) + rowp * PITCH + c8 * 4) << 2);
        cp16(dst, src, ok);
    }
    constexpr int BSLOTS = 2 * BROWS_PAD * 4;
    constexpr int BITER = (BSLOTS + 255) / 256;
#pragma unroll
    for (int it = 0; it < BITER; it++) {
        int slot = tid + it * 256;
        if (slot < BSLOTS) {
            int hilo = slot / (BROWS_PAD * 4);
            int rem = slot - hilo * (BROWS_PAD * 4);
            int ocr = rem >> 2, c8 = rem & 3;
            bool ok = (ocr < BROWS_DATA);
            const __nv_bfloat16* src = (hilo ? wl : wh) +
                (ok ? (((size_t)s * WROWS + ocr0 + ocr) * 32 + c8 * 8) : 0);
            uint32_t dst = bufAddr +
                (((hilo ? OFF_BL : OFF_BH) + ocr * PITCH + c8 * 4) << 2);
            cp16(dst, src, ok);
        }
    }
}

// ---------------------------------------------------------------------------
// Compute one slice: baseA/baseB are per-warp, per-buffer base addresses;
// every LDSM target is base + compile-time immediate.
// ---------------------------------------------------------------------------
template <int MT, int NT>
__device__ __forceinline__ void compute_slice(
    uint32_t baseA, uint32_t baseB, float (&acc)[MT][NT][4])
{
    constexpr int NP = NT / 2;
    constexpr uint32_t ROW16 = 16 * PITCH * 4;      // byte stride of 16 rows
    constexpr uint32_t DAL = (OFF_AL - OFF_AH) * 4; // A lo section offset
    constexpr uint32_t DBL = (OFF_BL - OFF_BH) * 4; // B lo section offset
#pragma unroll
    for (int ks = 0; ks < 2; ks++) {
        const uint32_t kb = ks * 32;                // k16-step byte offset
        uint32_t Ah[MT][4], Bh[NP][4];
#pragma unroll
        for (int mt = 0; mt < MT; mt++)
            LDSM4(Ah[mt], baseA + mt * ROW16 + kb);
#pragma unroll
        for (int p = 0; p < NP; p++)
            LDSM4(Bh[p], baseB + p * ROW16 + kb);
#pragma unroll
        for (int mt = 0; mt < MT; mt++)
#pragma unroll
            for (int p = 0; p < NP; p++) {
                MMAB(acc[mt][p * 2], Ah[mt], Bh[p][0], Bh[p][2]);
                MMAB(acc[mt][p * 2 + 1], Ah[mt], Bh[p][1], Bh[p][3]);
            }
        uint32_t Bl[NP][4];
#pragma unroll
        for (int p = 0; p < NP; p++)
            LDSM4(Bl[p], baseB + p * ROW16 + kb + DBL);
#pragma unroll
        for (int mt = 0; mt < MT; mt++)
#pragma unroll
            for (int p = 0; p < NP; p++) {
                MMAB(acc[mt][p * 2], Ah[mt], Bl[p][0], Bl[p][2]);
                MMAB(acc[mt][p * 2 + 1], Ah[mt], Bl[p][1], Bl[p][3]);
            }
        uint32_t Al[MT][4];
#pragma unroll
        for (int mt = 0; mt < MT; mt++)
            LDSM4(Al[mt], baseA + mt * ROW16 + kb + DAL);
#pragma unroll
        for (int mt = 0; mt < MT; mt++)
#pragma unroll
            for (int p = 0; p < NP; p++) {
                MMAB(acc[mt][p * 2], Al[mt], Bh[p][0], Bh[p][2]);
                MMAB(acc[mt][p * 2 + 1], Al[mt], Bh[p][1], Bh[p][3]);
            }
    }
}

#define GEOM_PROLOG()                                                       \
    int ah[4], aw[4]; bool apv[4];                                          \
    _Pragma("unroll")                                                       \
    for (int it = 0; it < 4; it++) {                                        \
        int rowp = ((threadIdx.x + it * 256) >> 2) & 127;                   \
        int pg = pixBase + rowp;                                            \
        apv[it] = pg < HW;                                                  \
        ah[it] = apv[it] ? pg / W : 0;                                      \
        aw[it] = apv[it] ? pg % W : 0;                                      \
    }

// Per-warp LDSM base offsets (within a buffer). lane-derived, computed once.
#define LDSM_BASES(pxw, ocw)                                                \
    const int lrow = lane & 15, lsel = lane >> 4;                           \
    const uint32_t aOff = (((pxw) + lrow) * PITCH + lsel * 4) * 4;          \
    const uint32_t bOff = (((ocw) + lrow) * PITCH + lsel * 4) * 4 + OFF_BH * 4;

// Manually x2-unrolled single-barrier double-buffered mainloop.
// Buffer parities are compile-time constants in each half.
#define MAINLOOP2(FILL, CSL)                                                \
    FILL(smA, 0); CP_COMMIT();                                              \
    for (int s = 0; s < NSLICE; s += 2) {                                   \
        CP_WAIT(0); __syncthreads();                                        \
        FILL(smA + BUF_U32 * 4, s + 1); CP_COMMIT();                        \
        CSL(smA);                                                           \
        CP_WAIT(0); __syncthreads();                                        \
        if (s + 2 < NSLICE) { FILL(smA, s + 2); CP_COMMIT(); }              \
        CSL(smA + BUF_U32 * 4);                                             \
    }

// ---------------------------------------------------------------------------
// Tower conv + fused GN-stats: grid (69, 2 halves, 2 towers)
// ---------------------------------------------------------------------------
__global__ __launch_bounds__(256, 2) void tower_mma(
    int step, const float* __restrict__ bC, const float* __restrict__ bB)
{
    extern __shared__ uint32_t sm[];
    const int tid = threadIdx.x, wid = tid >> 5, lane = tid & 31;
    const int g = lane >> 2, tg = lane & 3;
    const int bx = blockIdx.x, half = blockIdx.y, t = blockIdx.z;
    const int l = lvl_of_tile(bx);
    const int pixBase = (bx - (l ? c_tcum[l - 1] : 0)) * 128;
    const int H = c_Hc[l], W = H, HW = c_HWc[l];
    const size_t lb = (size_t)c_cum[l] * 256;

    const __nv_bfloat16* ihh = step ? &g_actH[t][lb] : &g_featH[lb];
    const __nv_bfloat16* ill = step ? &g_actL[t][lb] : &g_featL[lb];
    const __nv_bfloat16* wh = &g_wTh[t][step][0][0][0];
    const __nv_bfloat16* wl = &g_wTl[t][step][0][0][0];
    const int ocr0 = half * 128;

    GEOM_PROLOG();
    const uint32_t smA = smem_addr_of(sm);
    const int pxw = (wid & 1) * 64, ocw = (wid >> 1) * 32;
    LDSM_BASES(pxw, ocw);
    float acc[4][4][4] = {};

#define T_FILL(buf, s) fill_async<256, 128, 128>((buf), (s), ihh, ill, wh, wl, ocr0, ah, aw, apv, H, W)
#define T_CSL(buf) compute_slice<4, 4>((buf) + aOff, (buf) + bOff, acc)
    MAINLOOP2(T_FILL, T_CSL);
#undef T_FILL
#undef T_CSL

    const float* bias = (t ? bB : bC) + step * 256;
    float* raw = &g_rawD[t][lb];
#pragma unroll
    for (int nt = 0; nt < 4; nt++) {
        int oc = ocr0 + ocw + nt * 8 + tg * 2;
        float b0 = __ldg(&bias[oc]), b1 = __ldg(&bias[oc + 1]);
        float s = 0.f, ss = 0.f;
#pragma unroll
        for (int mt = 0; mt < 4; mt++) {
            int px = pixBase + pxw + mt * 16 + g;
            float v0 = acc[mt][nt][0] + b0, v1 = acc[mt][nt][1] + b1;
            float v2 = acc[mt][nt][2] + b0, v3 = acc[mt][nt][3] + b1;
            if (px < HW) {
                *(float2*)(raw + (size_t)px * 256 + oc) = make_float2(v0, v1);
                s += v0 + v1;
                ss = fmaf(v0, v0, ss); ss = fmaf(v1, v1, ss);
            }
            if (px + 8 < HW) {
                *(float2*)(raw + (size_t)(px + 8) * 256 + oc) = make_float2(v2, v3);
                s += v2 + v3;
                ss = fmaf(v2, v2, ss); ss = fmaf(v3, v3, ss);
            }
        }
#pragma unroll
        for (int o = 16; o > 0; o >>= 1) {
            s  += __shfl_xor_sync(0xffffffffu, s, o);
            ss += __shfl_xor_sync(0xffffffffu, ss, o);
        }
        if (lane == 0) {
            int gi = (ocr0 + ocw + nt * 8) >> 3;
            atomicAdd(&g_gsum[step][t][l][gi][0], s);
            atomicAdd(&g_gsum[step][t][l][gi][1], ss);
        }
    }
}

// ---------------------------------------------------------------------------
// Merged heads: grid (69, 2). y=0 score (cls, cols 0..79); y=1 pred+iou (box)
// ---------------------------------------------------------------------------
__global__ __launch_bounds__(256, 2) void head_all(
    const float* __restrict__ sb, const float* __restrict__ pb,
    const float* __restrict__ ib, const float* __restrict__ scales,
    float* __restrict__ out)
{
    extern __shared__ uint32_t sm[];
    const int tid = threadIdx.x, wid = tid >> 5, lane = tid & 31;
    const int g = lane >> 2, tg = lane & 3;
    const int bx = blockIdx.x, mode = blockIdx.y;
    const int l = lvl_of_tile(bx);
    const int pixBase = (bx - (l ? c_tcum[l - 1] : 0)) * 128;
    const int H = c_Hc[l], W = H, HW = c_HWc[l];
    const size_t lb = (size_t)c_cum[l] * 256;

    GEOM_PROLOG();
    const uint32_t smA = smem_addr_of(sm);

    if (mode == 0) {
        const __nv_bfloat16* ihh = &g_actH[0][lb];
        const __nv_bfloat16* ill = &g_actL[0][lb];
        const __nv_bfloat16* wh = &g_wSh[0][0][0];
        const __nv_bfloat16* wl = &g_wSl[0][0][0];
        const int pxw = (wid & 1) * 64, ocw = (wid >> 1) * 32;
        LDSM_BASES(pxw, ocw);
        float acc[4][4][4] = {};
#define S_FILL(buf, s) fill_async<128, 128, 128>((buf), (s), ihh, ill, wh, wl, 0, ah, aw, apv, H, W)
#define S_CSL(buf) compute_slice<4, 4>((buf) + aOff, (buf) + bOff, acc)
        MAINLOOP2(S_FILL, S_CSL);
#undef S_FILL
#undef S_CSL
#pragma unroll
        for (int mt = 0; mt < 4; mt++) {
            int px = pixBase + pxw + mt * 16 + g;
#pragma unroll
            for (int nt = 0; nt < 4; nt++) {
                int oc = ocw + nt * 8 + tg * 2;
                if (oc >= 80) continue;
                float b0 = __ldg(&sb[oc]), b1 = __ldg(&sb[oc + 1]);
                if (px < HW) {
                    float* d = out + (size_t)(c_cum[l] + px) * 85 + oc;
                    d[0] = acc[mt][nt][0] + b0;
                    d[1] = acc[mt][nt][1] + b1;
                }
                if (px + 8 < HW) {
                    float* d = out + (size_t)(c_cum[l] + px + 8) * 85 + oc;
                    d[0] = acc[mt][nt][2] + b0;
                    d[1] = acc[mt][nt][3] + b1;
                }
            }
        }
    } else {
        const __nv_bfloat16* ihh = &g_actH[1][lb];
        const __nv_bfloat16* ill = &g_actL[1][lb];
        const __nv_bfloat16* wh = &g_wPh[0][0][0];
        const __nv_bfloat16* wl = &g_wPl[0][0][0];
        const int pxw = wid * 16;
        LDSM_BASES(pxw, 0);
        float acc[1][2][4] = {};
#define P_FILL(buf, s) fill_async<8, 8, 16>((buf), (s), ihh, ill, wh, wl, 0, ah, aw, apv, H, W)
#define P_CSL(buf) compute_slice<1, 2>((buf) + aOff, (buf) + bOff, acc)
        MAINLOOP2(P_FILL, P_CSL);
#undef P_FILL
#undef P_CSL
        float sc = __ldg(&scales[l]), sf = c_strF[l];
#pragma unroll
        for (int halfp = 0; halfp < 2; halfp++) {
            int px = pixBase + pxw + halfp * 8 + g;
            if (px >= HW) continue;
            float* d = out + (size_t)(c_cum[l] + px) * 85;
#pragma unroll
            for (int j = 0; j < 2; j++) {
                int oc = tg * 2 + j;
                float v = acc[0][0][halfp * 2 + j];
                if (oc < 4)
                    d[80 + oc] = fmaxf((v + __ldg(&pb[oc])) * sc, 0.f) * sf;
                else if (oc == 4)
                    d[84] = v + __ldg(&ib[0]);
            }
        }
    }
}

// ---------------------------------------------------------------------------
// Combined prep: bx<268 weight prep (+zero), bx>=268 feature transpose.
// ---------------------------------------------------------------------------
__global__ __launch_bounds__(256) void prep_all(
    const float* __restrict__ cw, const float* __restrict__ bw,
    const float* __restrict__ sw, const float* __restrict__ pw,
    const float* __restrict__ iw,
    const float* __restrict__ f0, const float* __restrict__ f1,
    const float* __restrict__ f2, const float* __restrict__ f3,
    const float* __restrict__ f4)
{
    const int bx = blockIdx.x, tid = threadIdx.x;
    extern __shared__ float smw[];

    if (bx >= 268) {
        const int fb = bx - 268;
        const int l = fb / 200;
        const int p0 = (fb % 200) * 32;
        const int HW = c_HWc[l];
        if (p0 >= HW) return;
        const float* f = (l == 0) ? f0 : (l == 1) ? f1 : (l == 2) ? f2
                       : (l == 3) ? f3 : f4;
        float (*smf)[33] = (float (*)[33])smw;   // [256][33]
        const int pi = tid & 31, cb = tid >> 5;
#pragma unroll 8
        for (int j = 0; j < 32; j++) {
            int c = cb + j * 8;
            smf[c][pi] = (p0 + pi < HW) ? f[(size_t)c * HW + p0 + pi] : 0.f;
        }
        __syncthreads();
#pragma unroll 4
        for (int it = 0; it < 16; it++) {
            int pl = (tid >> 7) + it * 2;
            int c2 = (tid & 127) * 2;
            int p = p0 + pl;
            if (p < HW) {
                float v0 = smf[c2][pl], v1 = smf[c2 + 1][pl];
                __nv_bfloat16 h0, l0, h1, l1;
                bf_split(v0, h0, l0);
                bf_split(v1, h1, l1);
                size_t o = (size_t)(c_cum[l] + p) * 256 + c2;
                *(__nv_bfloat162*)&g_featH[o] = __nv_bfloat162(h0, h1);
                *(__nv_bfloat162*)&g_featL[o] = __nv_bfloat162(l0, l1);
            }
        }
        return;
    }
    if (bx == 267) {
        float* z = (float*)g_gsum;
        for (int i = tid; i < 4 * 2 * 5 * 32 * 2; i += 256) z[i] = 0.f;
        return;
    }
    if (bx < 256) {
        int t = bx >> 7, st = (bx >> 5) & 3, oc0 = (bx & 31) * 8;
        const float* src = (t ? bw : cw) + (size_t)st * 256 * 2304 + (size_t)oc0 * 2304;
        for (int i = tid; i < 8 * 2304; i += 256) smw[i] = src[i];
        __syncthreads();
        int c = tid & 31, ocr = tid >> 5;
        for (int s = 0; s < NSLICE; s++) {
            int rs = s >> 3, ic0 = (s & 7) * 32;
            float v = smw[ocr * 2304 + (ic0 + c) * 9 + rs];
            __nv_bfloat16 h, lo; bf_split(v, h, lo);
            g_wTh[t][st][s][oc0 + ocr][c] = h;
            g_wTl[t][st][s][oc0 + ocr][c] = lo;
        }
    } else if (bx < 266) {
        int oc0 = (bx - 256) * 8;
        for (int i = tid; i < 8 * 2304; i += 256) smw[i] = sw[(size_t)oc0 * 2304 + i];
        __syncthreads();
        int c = tid & 31, ocr = tid >> 5;
        for (int s = 0; s < NSLICE; s++) {
            int rs = s >> 3, ic0 = (s & 7) * 32;
            float v = smw[ocr * 2304 + (ic0 + c) * 9 + rs];
            __nv_bfloat16 h, lo; bf_split(v, h, lo);
            g_wSh[s][oc0 + ocr][c] = h;
            g_wSl[s][oc0 + ocr][c] = lo;
        }
    } else {
        for (int i = tid; i < 8 * 2304; i += 256) {
            int r = i / 2304, k = i - r * 2304;
            float v = 0.f;
            if (r < 4) v = pw[(size_t)r * 2304 + k];
            else if (r == 4) v = iw[k];
            smw[i] = v;
        }
        __syncthreads();
        int c = tid & 31, ocr = tid >> 5;
        for (int s = 0; s < NSLICE; s++) {
            int rs = s >> 3, ic0 = (s & 7) * 32;
            float v = smw[ocr * 2304 + (ic0 + c) * 9 + rs];
            __nv_bfloat16 h, lo; bf_split(v, h, lo);
            g_wPh[s][ocr][c] = h;
            g_wPl[s][ocr][c] = lo;
        }
    }
}

// ---------------------------------------------------------------------------
// GN apply + ReLU + bf16 split, 4 ch/thread.
// ---------------------------------------------------------------------------
__global__ __launch_bounds__(256) void gn_apply(
    const float* __restrict__ gwC, const float* __restrict__ gbC,
    const float* __restrict__ gwB, const float* __restrict__ gbB, int step)
{
    const int t = blockIdx.y;
    const int idx = blockIdx.x * 256 + threadIdx.x;
    const int p = idx >> 6;
    if (p >= NPIX) return;
    const int c = (idx & 63) * 4;
    const int l = lvl_of_pix(p);
    const float* gw = (t ? gwB : gwC) + step * 256;
    const float* gb = (t ? gbB : gbC) + step * 256;

    const int gi = c >> 3;
    float s  = g_gsum[step][t][l][gi][0];
    float ss = g_gsum[step][t][l][gi][1];
    float inv_n = 1.f / (float)(8 * c_HWc[l]);
    float mean = s * inv_n;
    float var = ss * inv_n - mean * mean;
    float rstd = rsqrtf(fmaxf(var, 0.f) + 1e-5f);

    float4 gwv = *(const float4*)&gw[c];
    float4 gbv = *(const float4*)&gb[c];
    size_t o = (size_t)p * 256 + c;
    float4 r = *(const float4*)&g_rawD[t][o];

    float v0 = fmaxf(fmaf(r.x, gwv.x * rstd, fmaf(-mean, gwv.x * rstd, gbv.x)), 0.f);
    float v1 = fmaxf(fmaf(r.y, gwv.y * rstd, fmaf(-mean, gwv.y * rstd, gbv.y)), 0.f);
    float v2 = fmaxf(fmaf(r.z, gwv.z * rstd, fmaf(-mean, gwv.z * rstd, gbv.z)), 0.f);
    float v3 = fmaxf(fmaf(r.w, gwv.w * rstd, fmaf(-mean, gwv.w * rstd, gbv.w)), 0.f);

    __nv_bfloat16 h0, l0, h1, l1, h2, l2, h3, l3;
    bf_split(v0, h0, l0); bf_split(v1, h1, l1);
    bf_split(v2, h2, l2); bf_split(v3, h3, l3);
    __nv_bfloat162 hv0(h0, h1), hv1(h2, h3), lv0(l0, l1), lv1(l2, l3);
    uint32_t hu0, hu1, lu0, lu1;
    memcpy(&hu0, &hv0, 4); memcpy(&hu1, &hv1, 4);
    memcpy(&lu0, &lv0, 4); memcpy(&lu1, &lv1, 4);
    *(uint2*)&g_actH[t][o] = make_uint2(hu0, hu1);
    *(uint2*)&g_actL[t][o] = make_uint2(lu0, lu1);
}

// ---------------------------------------------------------------------------
// Host driver: 10 launches
// ---------------------------------------------------------------------------
extern "C" void kernel_launch(void* const* d_in, const int* in_sizes, int n_in,
                              void* d_out, int out_size)
{
    const float* f0 = (const float*)d_in[0];
    const float* f1 = (const float*)d_in[1];
    const float* f2 = (const float*)d_in[2];
    const float* f3 = (const float*)d_in[3];
    const float* f4 = (const float*)d_in[4];
    const float* cls_w    = (const float*)d_in[5];
    const float* cls_b    = (const float*)d_in[6];
    const float* cls_gn_w = (const float*)d_in[7];
    const float* cls_gn_b = (const float*)d_in[8];
    const float* box_w    = (const float*)d_in[9];
    const float* box_b    = (const float*)d_in[10];
    const float* box_gn_w = (const float*)d_in[11];
    const float* box_gn_b = (const float*)d_in[12];
    const float* score_w  = (const float*)d_in[13];
    const float* score_b  = (const float*)d_in[14];
    const float* pred_w   = (const float*)d_in[15];
    const float* pred_b   = (const float*)d_in[16];
    const float* iou_w    = (const float*)d_in[17];
    const float* iou_b    = (const float*)d_in[18];
    const float* scales   = (const float*)d_in[19];
    float* out = (float*)d_out;

    static bool attr_done = false;
    if (!attr_done) {
        cudaFuncSetAttribute(tower_mma, cudaFuncAttributeMaxDynamicSharedMemorySize, SMEM_BYTES);
        cudaFuncSetAttribute(head_all,  cudaFuncAttributeMaxDynamicSharedMemorySize, SMEM_BYTES);
        cudaFuncSetAttribute(prep_all,  cudaFuncAttributeMaxDynamicSharedMemorySize, PREP_SMEM);
        attr_done = true;
    }

    prep_all<<<268 + 1000, 256, PREP_SMEM>>>(cls_w, box_w, score_w, pred_w, iou_w,
                                             f0, f1, f2, f3, f4);

    for (int step = 0; step < 4; step++) {
        tower_mma<<<dim3(69, 2, 2), 256, SMEM_BYTES>>>(step, cls_b, box_b);
        gn_apply<<<dim3((NPIX * 64 + 255) / 256, 2), 256>>>(cls_gn_w, cls_gn_b,
                                                            box_gn_w, box_gn_b, step);
    }
    head_all<<<dim3(69, 2), 256, SMEM_BYTES>>>(score_b, pred_b, iou_b, scales, out);
}

// round 14
// speedup vs baseline: 1.5162x; 1.5162x over previous
#include <cuda_runtime.h>
#include <cuda_bf16.h>
#include <stdint.h>

#define CH 256
#define NPIX 8525
#define NSLICE 72

// ---- scratch (bf16 hi/lo operand storage) ---------------------------------
__device__ __align__(16) __nv_bfloat16 g_wTh[2][4][NSLICE][256][32];
__device__ __align__(16) __nv_bfloat16 g_wTl[2][4][NSLICE][256][32];
__device__ __align__(16) __nv_bfloat16 g_wSh[NSLICE][128][32];   // 80 used
__device__ __align__(16) __nv_bfloat16 g_wSl[NSLICE][128][32];
__device__ __align__(16) __nv_bfloat16 g_wPh[NSLICE][8][32];     // pred4+iou1+pad
__device__ __align__(16) __nv_bfloat16 g_wPl[NSLICE][8][32];
__device__ __align__(16) __nv_bfloat16 g_featH[NPIX * CH];
__device__ __align__(16) __nv_bfloat16 g_featL[NPIX * CH];
__device__ __align__(16) __nv_bfloat16 g_actH[2][NPIX * CH];
__device__ __align__(16) __nv_bfloat16 g_actL[2][NPIX * CH];
__device__ float g_rawD[2][NPIX * CH];        // pre-GN fp32 [pix][ch]
__device__ float g_gsum[4][2][5][32][2];      // [step][tower][lvl][group]{s,ss}

__constant__ int   c_Hc[5]   = {80, 40, 20, 10, 5};
__constant__ int   c_HWc[5]  = {6400, 1600, 400, 100, 25};
__constant__ int   c_cum[5]  = {0, 6400, 8000, 8400, 8500};
__constant__ int   c_tcum[5] = {50, 63, 67, 68, 69};
__constant__ float c_strF[5] = {8.f, 16.f, 32.f, 64.f, 128.f};

#define MMAB(c, a, b0v, b1v) \
    asm volatile("mma.sync.aligned.m16n8k16.row.col.f32.bf16.bf16.f32 " \
        "{%0,%1,%2,%3},{%4,%5,%6,%7},{%8,%9},{%0,%1,%2,%3};" \
        : "+f"((c)[0]), "+f"((c)[1]), "+f"((c)[2]), "+f"((c)[3]) \
        : "r"((a)[0]), "r"((a)[1]), "r"((a)[2]), "r"((a)[3]), \
          "r"(b0v), "r"(b1v))

#define LDSM4(r, a) \
    asm volatile("ldmatrix.sync.aligned.m8n8.x4.shared.b16 {%0,%1,%2,%3}, [%4];" \
        : "=r"((r)[0]), "=r"((r)[1]), "=r"((r)[2]), "=r"((r)[3]) : "r"(a))

#define CP_COMMIT() asm volatile("cp.async.commit_group;" ::: "memory")
#define CP_WAIT(n)  asm volatile("cp.async.wait_group %0;" :: "n"(n) : "memory")

__device__ __forceinline__ void cp16(uint32_t dst, const void* src, bool ok) {
    asm volatile("cp.async.cg.shared.global [%0], [%1], 16, %2;"
                 :: "r"(dst), "l"(src), "r"(ok ? 16 : 0) : "memory");
}

// ---- SMEM layout (u32 units): pitch 20 u32/row ----------------------------
#define PITCH 20
#define OFF_AH 0
#define OFF_AL 2560
#define OFF_BH 5120
#define OFF_BL 7680
#define BUF_U32 10240
#define SMEM_BYTES (2 * BUF_U32 * 4)   // 81920
#define PREP_SMEM (8 * 2304 * 4)       // 73728

__device__ __forceinline__ uint32_t smem_addr_of(const void* p) {
    uint32_t a;
    asm("{ .reg .u64 t; cvta.to.shared.u64 t, %1; cvt.u32.u64 %0, t; }" : "=r"(a) : "l"(p));
    return a;
}
__device__ __forceinline__ int lvl_of_tile(int bx) {
    int l = 0;
    if (bx >= c_tcum[0]) l = 1;
    if (bx >= c_tcum[1]) l = 2;
    if (bx >= c_tcum[2]) l = 3;
    if (bx >= c_tcum[3]) l = 4;
    return l;
}
__device__ __forceinline__ int lvl_of_pix(int p) {
    int l = 0;
    if (p >= 6400) l = 1;
    if (p >= 8000) l = 2;
    if (p >= 8400) l = 3;
    if (p >= 8500) l = 4;
    return l;
}
__device__ __forceinline__ void bf_split(float v, __nv_bfloat16& h, __nv_bfloat16& lo) {
    h = __float2bfloat16_rn(v);
    lo = __float2bfloat16_rn(v - __bfloat162float(h));
}

// ---------------------------------------------------------------------------
// Async fill of one stage (bufAddr = SMEM byte addr of stage base)
// ---------------------------------------------------------------------------
template <int WROWS, int BROWS_DATA, int BROWS_PAD>
__device__ __forceinline__ void fill_async(
    uint32_t bufAddr, int s,
    const __nv_bfloat16* __restrict__ ihh, const __nv_bfloat16* __restrict__ ill,
    const __nv_bfloat16* __restrict__ wh, const __nv_bfloat16* __restrict__ wl,
    int ocr0, const int* ah, const int* aw, const bool* apv, int H, int W)
{
    const int tid = threadIdx.x;
    const int rs = s >> 3, ic0 = (s & 7) * 32;
    const int dr = rs / 3 - 1, ds = rs % 3 - 1;

#pragma unroll
    for (int it = 0; it < 4; it++) {
        int slot = tid + it * 256;
        int hilo = slot >> 9, rowp = (slot >> 2) & 127, c8 = slot & 3;
        int hh = ah[it] + dr, ww = aw[it] + ds;
        bool ok = apv[it] && (unsigned)hh < (unsigned)H && (unsigned)ww < (unsigned)W;
        const __nv_bfloat16* src = (hilo ? ill : ihh) +
            (ok ? ((size_t)(hh * W + ww) * 256 + ic0 + c8 * 8) : 0);
        uint32_t dst = bufAddr +
            (((hilo ? OFF_AL : OFF_AH) + rowp * PITCH + c8 * 4) << 2);
        cp16(dst, src, ok);
    }
    constexpr int BSLOTS = 2 * BROWS_PAD * 4;
    constexpr int BITER = (BSLOTS + 255) / 256;
#pragma unroll
    for (int it = 0; it < BITER; it++) {
        int slot = tid + it * 256;
        if (slot < BSLOTS) {
            int hilo = slot / (BROWS_PAD * 4);
            int rem = slot - hilo * (BROWS_PAD * 4);
            int ocr = rem >> 2, c8 = rem & 3;
            bool ok = (ocr < BROWS_DATA);
            const __nv_bfloat16* src = (hilo ? wl : wh) +
                (ok ? (((size_t)s * WROWS + ocr0 + ocr) * 32 + c8 * 8) : 0);
            uint32_t dst = bufAddr +
                (((hilo ? OFF_BL : OFF_BH) + ocr * PITCH + c8 * 4) << 2);
            cp16(dst, src, ok);
        }
    }
}

// ---------------------------------------------------------------------------
// Compute one slice from per-warp base addresses: every LDSM target is
// base + compile-time immediate (folds addressing into the instruction).
// ---------------------------------------------------------------------------
template <int MT, int NT>
__device__ __forceinline__ void compute_slice(
    uint32_t baseA, uint32_t baseB, float (&acc)[MT][NT][4])
{
    constexpr int NP = NT / 2;
    constexpr uint32_t ROW16 = 16 * PITCH * 4;
    constexpr uint32_t DAL = (OFF_AL - OFF_AH) * 4;
    constexpr uint32_t DBL = (OFF_BL - OFF_BH) * 4;
#pragma unroll
    for (int ks = 0; ks < 2; ks++) {
        const uint32_t kb = ks * 32;
        uint32_t Ah[MT][4], Bh[NP][4];
#pragma unroll
        for (int mt = 0; mt < MT; mt++)
            LDSM4(Ah[mt], baseA + mt * ROW16 + kb);
#pragma unroll
        for (int p = 0; p < NP; p++)
            LDSM4(Bh[p], baseB + p * ROW16 + kb);
#pragma unroll
        for (int mt = 0; mt < MT; mt++)
#pragma unroll
            for (int p = 0; p < NP; p++) {
                MMAB(acc[mt][p * 2], Ah[mt], Bh[p][0], Bh[p][2]);
                MMAB(acc[mt][p * 2 + 1], Ah[mt], Bh[p][1], Bh[p][3]);
            }
        uint32_t Bl[NP][4];
#pragma unroll
        for (int p = 0; p < NP; p++)
            LDSM4(Bl[p], baseB + p * ROW16 + kb + DBL);
#pragma unroll
        for (int mt = 0; mt < MT; mt++)
#pragma unroll
            for (int p = 0; p < NP; p++) {
                MMAB(acc[mt][p * 2], Ah[mt], Bl[p][0], Bl[p][2]);
                MMAB(acc[mt][p * 2 + 1], Ah[mt], Bl[p][1], Bl[p][3]);
            }
        uint32_t Al[MT][4];
#pragma unroll
        for (int mt = 0; mt < MT; mt++)
            LDSM4(Al[mt], baseA + mt * ROW16 + kb + DAL);
#pragma unroll
        for (int mt = 0; mt < MT; mt++)
#pragma unroll
            for (int p = 0; p < NP; p++) {
                MMAB(acc[mt][p * 2], Al[mt], Bh[p][0], Bh[p][2]);
                MMAB(acc[mt][p * 2 + 1], Al[mt], Bh[p][1], Bh[p][3]);
            }
    }
}

#define GEOM_PROLOG()                                                       \
    int ah[4], aw[4]; bool apv[4];                                          \
    _Pragma("unroll")                                                       \
    for (int it = 0; it < 4; it++) {                                        \
        int rowp = ((threadIdx.x + it * 256) >> 2) & 127;                   \
        int pg = pixBase + rowp;                                            \
        apv[it] = pg < HW;                                                  \
        ah[it] = apv[it] ? pg / W : 0;                                      \
        aw[it] = apv[it] ? pg % W : 0;                                      \
    }

// Per-warp LDSM base offsets (within a buffer), computed once.
#define LDSM_BASES(pxw, ocw)                                                \
    const int lrow = lane & 15, lsel = lane >> 4;                           \
    const uint32_t aOff = (((pxw) + lrow) * PITCH + lsel * 4) * 4;          \
    const uint32_t bOff = (((ocw) + lrow) * PITCH + lsel * 4) * 4 + OFF_BH * 4;

// Single-barrier double-buffered cp.async mainloop (R12 structure):
//   wait(fill s) -> sync -> issue fill(s+1) -> compute(s)
#define MAINLOOP(FILL_CALL_NEXT, COMPUTE_CALL)                              \
    for (int s = 0; s < NSLICE; s++) {                                      \
        CP_WAIT(0);                                                         \
        __syncthreads();                                                    \
        if (s + 1 < NSLICE) {                                               \
            const int sn = s + 1;                                           \
            const uint32_t bufN = smA + ((sn & 1) * BUF_U32) * 4;           \
            FILL_CALL_NEXT;                                                 \
            CP_COMMIT();                                                    \
        }                                                                   \
        const uint32_t bufC = smA + ((s & 1) * BUF_U32) * 4;                \
        COMPUTE_CALL;                                                       \
    }

// ---------------------------------------------------------------------------
// Tower conv + fused GN-stats: grid (69, 2 halves, 2 towers)
// ---------------------------------------------------------------------------
__global__ __launch_bounds__(256, 2) void tower_mma(
    int step, const float* __restrict__ bC, const float* __restrict__ bB)
{
    extern __shared__ uint32_t sm[];
    const int tid = threadIdx.x, wid = tid >> 5, lane = tid & 31;
    const int g = lane >> 2, tg = lane & 3;
    const int bx = blockIdx.x, half = blockIdx.y, t = blockIdx.z;
    const int l = lvl_of_tile(bx);
    const int pixBase = (bx - (l ? c_tcum[l - 1] : 0)) * 128;
    const int H = c_Hc[l], W = H, HW = c_HWc[l];
    const size_t lb = (size_t)c_cum[l] * 256;

    const __nv_bfloat16* ihh = step ? &g_actH[t][lb] : &g_featH[lb];
    const __nv_bfloat16* ill = step ? &g_actL[t][lb] : &g_featL[lb];
    const __nv_bfloat16* wh = &g_wTh[t][step][0][0][0];
    const __nv_bfloat16* wl = &g_wTl[t][step][0][0][0];
    const int ocr0 = half * 128;

    GEOM_PROLOG();
    const uint32_t smA = smem_addr_of(sm);
    const int pxw = (wid & 1) * 64, ocw = (wid >> 1) * 32;
    LDSM_BASES(pxw, ocw);
    float acc[4][4][4] = {};

    fill_async<256, 128, 128>(smA, 0, ihh, ill, wh, wl, ocr0, ah, aw, apv, H, W);
    CP_COMMIT();
    MAINLOOP(
        (fill_async<256, 128, 128>(bufN, sn, ihh, ill, wh, wl, ocr0, ah, aw, apv, H, W)),
        (compute_slice<4, 4>(bufC + aOff, bufC + bOff, acc)));

    const float* bias = (t ? bB : bC) + step * 256;
    float* raw = &g_rawD[t][lb];
#pragma unroll
    for (int nt = 0; nt < 4; nt++) {
        int oc = ocr0 + ocw + nt * 8 + tg * 2;
        float b0 = __ldg(&bias[oc]), b1 = __ldg(&bias[oc + 1]);
        float s = 0.f, ss = 0.f;
#pragma unroll
        for (int mt = 0; mt < 4; mt++) {
            int px = pixBase + pxw + mt * 16 + g;
            float v0 = acc[mt][nt][0] + b0, v1 = acc[mt][nt][1] + b1;
            float v2 = acc[mt][nt][2] + b0, v3 = acc[mt][nt][3] + b1;
            if (px < HW) {
                *(float2*)(raw + (size_t)px * 256 + oc) = make_float2(v0, v1);
                s += v0 + v1;
                ss = fmaf(v0, v0, ss); ss = fmaf(v1, v1, ss);
            }
            if (px + 8 < HW) {
                *(float2*)(raw + (size_t)(px + 8) * 256 + oc) = make_float2(v2, v3);
                s += v2 + v3;
                ss = fmaf(v2, v2, ss); ss = fmaf(v3, v3, ss);
            }
        }
#pragma unroll
        for (int o = 16; o > 0; o >>= 1) {
            s  += __shfl_xor_sync(0xffffffffu, s, o);
            ss += __shfl_xor_sync(0xffffffffu, ss, o);
        }
        if (lane == 0) {
            int gi = (ocr0 + ocw + nt * 8) >> 3;
            atomicAdd(&g_gsum[step][t][l][gi][0], s);
            atomicAdd(&g_gsum[step][t][l][gi][1], ss);
        }
    }
}

// ---------------------------------------------------------------------------
// Merged heads: grid (69, 2). y=0 score (cls, cols 0..79); y=1 pred+iou (box)
// ---------------------------------------------------------------------------
__global__ __launch_bounds__(256, 2) void head_all(
    const float* __restrict__ sb, const float* __restrict__ pb,
    const float* __restrict__ ib, const float* __restrict__ scales,
    float* __restrict__ out)
{
    extern __shared__ uint32_t sm[];
    const int tid = threadIdx.x, wid = tid >> 5, lane = tid & 31;
    const int g = lane >> 2, tg = lane & 3;
    const int bx = blockIdx.x, mode = blockIdx.y;
    const int l = lvl_of_tile(bx);
    const int pixBase = (bx - (l ? c_tcum[l - 1] : 0)) * 128;
    const int H = c_Hc[l], W = H, HW = c_HWc[l];
    const size_t lb = (size_t)c_cum[l] * 256;

    GEOM_PROLOG();
    const uint32_t smA = smem_addr_of(sm);

    if (mode == 0) {
        const __nv_bfloat16* ihh = &g_actH[0][lb];
        const __nv_bfloat16* ill = &g_actL[0][lb];
        const __nv_bfloat16* wh = &g_wSh[0][0][0];
        const __nv_bfloat16* wl = &g_wSl[0][0][0];
        const int pxw = (wid & 1) * 64, ocw = (wid >> 1) * 32;
        LDSM_BASES(pxw, ocw);
        float acc[4][4][4] = {};
        fill_async<128, 128, 128>(smA, 0, ihh, ill, wh, wl, 0, ah, aw, apv, H, W);
        CP_COMMIT();
        MAINLOOP(
            (fill_async<128, 128, 128>(bufN, sn, ihh, ill, wh, wl, 0, ah, aw, apv, H, W)),
            (compute_slice<4, 4>(bufC + aOff, bufC + bOff, acc)));
#pragma unroll
        for (int mt = 0; mt < 4; mt++) {
            int px = pixBase + pxw + mt * 16 + g;
#pragma unroll
            for (int nt = 0; nt < 4; nt++) {
                int oc = ocw + nt * 8 + tg * 2;
                if (oc >= 80) continue;
                float b0 = __ldg(&sb[oc]), b1 = __ldg(&sb[oc + 1]);
                if (px < HW) {
                    float* d = out + (size_t)(c_cum[l] + px) * 85 + oc;
                    d[0] = acc[mt][nt][0] + b0;
                    d[1] = acc[mt][nt][1] + b1;
                }
                if (px + 8 < HW) {
                    float* d = out + (size_t)(c_cum[l] + px + 8) * 85 + oc;
                    d[0] = acc[mt][nt][2] + b0;
                    d[1] = acc[mt][nt][3] + b1;
                }
            }
        }
    } else {
        const __nv_bfloat16* ihh = &g_actH[1][lb];
        const __nv_bfloat16* ill = &g_actL[1][lb];
        const __nv_bfloat16* wh = &g_wPh[0][0][0];
        const __nv_bfloat16* wl = &g_wPl[0][0][0];
        const int pxw = wid * 16;
        LDSM_BASES(pxw, 0);
        float acc[1][2][4] = {};
        fill_async<8, 8, 16>(smA, 0, ihh, ill, wh, wl, 0, ah, aw, apv, H, W);
        CP_COMMIT();
        MAINLOOP(
            (fill_async<8, 8, 16>(bufN, sn, ihh, ill, wh, wl, 0, ah, aw, apv, H, W)),
            (compute_slice<1, 2>(bufC + aOff, bufC + bOff, acc)));
        float sc = __ldg(&scales[l]), sf = c_strF[l];
#pragma unroll
        for (int halfp = 0; halfp < 2; halfp++) {
            int px = pixBase + pxw + halfp * 8 + g;
            if (px >= HW) continue;
            float* d = out + (size_t)(c_cum[l] + px) * 85;
#pragma unroll
            for (int j = 0; j < 2; j++) {
                int oc = tg * 2 + j;
                float v = acc[0][0][halfp * 2 + j];
                if (oc < 4)
                    d[80 + oc] = fmaxf((v + __ldg(&pb[oc])) * sc, 0.f) * sf;
                else if (oc == 4)
                    d[84] = v + __ldg(&ib[0]);
            }
        }
    }
}

// ---------------------------------------------------------------------------
// Combined prep: bx<268 weight prep (+zero), bx>=268 feature transpose.
// ---------------------------------------------------------------------------
__global__ __launch_bounds__(256) void prep_all(
    const float* __restrict__ cw, const float* __restrict__ bw,
    const float* __restrict__ sw, const float* __restrict__ pw,
    const float* __restrict__ iw,
    const float* __restrict__ f0, const float* __restrict__ f1,
    const float* __restrict__ f2, const float* __restrict__ f3,
    const float* __restrict__ f4)
{
    const int bx = blockIdx.x, tid = threadIdx.x;
    extern __shared__ float smw[];

    if (bx >= 268) {
        const int fb = bx - 268;
        const int l = fb / 200;
        const int p0 = (fb % 200) * 32;
        const int HW = c_HWc[l];
        if (p0 >= HW) return;
        const float* f = (l == 0) ? f0 : (l == 1) ? f1 : (l == 2) ? f2
                       : (l == 3) ? f3 : f4;
        float (*smf)[33] = (float (*)[33])smw;   // [256][33]
        const int pi = tid & 31, cb = tid >> 5;
#pragma unroll 8
        for (int j = 0; j < 32; j++) {
            int c = cb + j * 8;
            smf[c][pi] = (p0 + pi < HW) ? f[(size_t)c * HW + p0 + pi] : 0.f;
        }
        __syncthreads();
#pragma unroll 4
        for (int it = 0; it < 16; it++) {
            int pl = (tid >> 7) + it * 2;
            int c2 = (tid & 127) * 2;
            int p = p0 + pl;
            if (p < HW) {
                float v0 = smf[c2][pl], v1 = smf[c2 + 1][pl];
                __nv_bfloat16 h0, l0, h1, l1;
                bf_split(v0, h0, l0);
                bf_split(v1, h1, l1);
                size_t o = (size_t)(c_cum[l] + p) * 256 + c2;
                *(__nv_bfloat162*)&g_featH[o] = __nv_bfloat162(h0, h1);
                *(__nv_bfloat162*)&g_featL[o] = __nv_bfloat162(l0, l1);
            }
        }
        return;
    }
    if (bx == 267) {
        float* z = (float*)g_gsum;
        for (int i = tid; i < 4 * 2 * 5 * 32 * 2; i += 256) z[i] = 0.f;
        return;
    }
    if (bx < 256) {
        int t = bx >> 7, st = (bx >> 5) & 3, oc0 = (bx & 31) * 8;
        const float* src = (t ? bw : cw) + (size_t)st * 256 * 2304 + (size_t)oc0 * 2304;
        for (int i = tid; i < 8 * 2304; i += 256) smw[i] = src[i];
        __syncthreads();
        int c = tid & 31, ocr = tid >> 5;
        for (int s = 0; s < NSLICE; s++) {
            int rs = s >> 3, ic0 = (s & 7) * 32;
            float v = smw[ocr * 2304 + (ic0 + c) * 9 + rs];
            __nv_bfloat16 h, lo; bf_split(v, h, lo);
            g_wTh[t][st][s][oc0 + ocr][c] = h;
            g_wTl[t][st][s][oc0 + ocr][c] = lo;
        }
    } else if (bx < 266) {
        int oc0 = (bx - 256) * 8;
        for (int i = tid; i < 8 * 2304; i += 256) smw[i] = sw[(size_t)oc0 * 2304 + i];
        __syncthreads();
        int c = tid & 31, ocr = tid >> 5;
        for (int s = 0; s < NSLICE; s++) {
            int rs = s >> 3, ic0 = (s & 7) * 32;
            float v = smw[ocr * 2304 + (ic0 + c) * 9 + rs];
            __nv_bfloat16 h, lo; bf_split(v, h, lo);
            g_wSh[s][oc0 + ocr][c] = h;
            g_wSl[s][oc0 + ocr][c] = lo;
        }
    } else {
        for (int i = tid; i < 8 * 2304; i += 256) {
            int r = i / 2304, k = i - r * 2304;
            float v = 0.f;
            if (r < 4) v = pw[(size_t)r * 2304 + k];
            else if (r == 4) v = iw[k];
            smw[i] = v;
        }
        __syncthreads();
        int c = tid & 31, ocr = tid >> 5;
        for (int s = 0; s < NSLICE; s++) {
            int rs = s >> 3, ic0 = (s & 7) * 32;
            float v = smw[ocr * 2304 + (ic0 + c) * 9 + rs];
            __nv_bfloat16 h, lo; bf_split(v, h, lo);
            g_wPh[s][ocr][c] = h;
            g_wPl[s][ocr][c] = lo;
        }
    }
}

// ---------------------------------------------------------------------------
// GN apply + ReLU + bf16 split, 4 ch/thread.
// ---------------------------------------------------------------------------
__global__ __launch_bounds__(256) void gn_apply(
    const float* __restrict__ gwC, const float* __restrict__ gbC,
    const float* __restrict__ gwB, const float* __restrict__ gbB, int step)
{
    const int t = blockIdx.y;
    const int idx = blockIdx.x * 256 + threadIdx.x;
    const int p = idx >> 6;
    if (p >= NPIX) return;
    const int c = (idx & 63) * 4;
    const int l = lvl_of_pix(p);
    const float* gw = (t ? gwB : gwC) + step * 256;
    const float* gb = (t ? gbB : gbC) + step * 256;

    const int gi = c >> 3;
    float s  = g_gsum[step][t][l][gi][0];
    float ss = g_gsum[step][t][l][gi][1];
    float inv_n = 1.f / (float)(8 * c_HWc[l]);
    float mean = s * inv_n;
    float var = ss * inv_n - mean * mean;
    float rstd = rsqrtf(fmaxf(var, 0.f) + 1e-5f);

    float4 gwv = *(const float4*)&gw[c];
    float4 gbv = *(const float4*)&gb[c];
    size_t o = (size_t)p * 256 + c;
    float4 r = *(const float4*)&g_rawD[t][o];

    float v0 = fmaxf(fmaf(r.x, gwv.x * rstd, fmaf(-mean, gwv.x * rstd, gbv.x)), 0.f);
    float v1 = fmaxf(fmaf(r.y, gwv.y * rstd, fmaf(-mean, gwv.y * rstd, gbv.y)), 0.f);
    float v2 = fmaxf(fmaf(r.z, gwv.z * rstd, fmaf(-mean, gwv.z * rstd, gbv.z)), 0.f);
    float v3 = fmaxf(fmaf(r.w, gwv.w * rstd, fmaf(-mean, gwv.w * rstd, gbv.w)), 0.f);

    __nv_bfloat16 h0, l0, h1, l1, h2, l2, h3, l3;
    bf_split(v0, h0, l0); bf_split(v1, h1, l1);
    bf_split(v2, h2, l2); bf_split(v3, h3, l3);
    __nv_bfloat162 hv0(h0, h1), hv1(h2, h3), lv0(l0, l1), lv1(l2, l3);
    uint32_t hu0, hu1, lu0, lu1;
    memcpy(&hu0, &hv0, 4); memcpy(&hu1, &hv1, 4);
    memcpy(&lu0, &lv0, 4); memcpy(&lu1, &lv1, 4);
    *(uint2*)&g_actH[t][o] = make_uint2(hu0, hu1);
    *(uint2*)&g_actL[t][o] = make_uint2(lu0, lu1);
}

// ---------------------------------------------------------------------------
// Host driver: 10 launches
// ---------------------------------------------------------------------------
extern "C" void kernel_launch(void* const* d_in, const int* in_sizes, int n_in,
                              void* d_out, int out_size)
{
    const float* f0 = (const float*)d_in[0];
    const float* f1 = (const float*)d_in[1];
    const float* f2 = (const float*)d_in[2];
    const float* f3 = (const float*)d_in[3];
    const float* f4 = (const float*)d_in[4];
    const float* cls_w    = (const float*)d_in[5];
    const float* cls_b    = (const float*)d_in[6];
    const float* cls_gn_w = (const float*)d_in[7];
    const float* cls_gn_b = (const float*)d_in[8];
    const float* box_w    = (const float*)d_in[9];
    const float* box_b    = (const float*)d_in[10];
    const float* box_gn_w = (const float*)d_in[11];
    const float* box_gn_b = (const float*)d_in[12];
    const float* score_w  = (const float*)d_in[13];
    const float* score_b  = (const float*)d_in[14];
    const float* pred_w   = (const float*)d_in[15];
    const float* pred_b   = (const float*)d_in[16];
    const float* iou_w    = (const float*)d_in[17];
    const float* iou_b    = (const float*)d_in[18];
    const float* scales   = (const float*)d_in[19];
    float* out = (float*)d_out;

    static bool attr_done = false;
    if (!attr_done) {
        cudaFuncSetAttribute(tower_mma, cudaFuncAttributeMaxDynamicSharedMemorySize, SMEM_BYTES);
        cudaFuncSetAttribute(head_all,  cudaFuncAttributeMaxDynamicSharedMemorySize, SMEM_BYTES);
        cudaFuncSetAttribute(prep_all,  cudaFuncAttributeMaxDynamicSharedMemorySize, PREP_SMEM);
        attr_done = true;
    }

    prep_all<<<268 + 1000, 256, PREP_SMEM>>>(cls_w, box_w, score_w, pred_w, iou_w,
                                             f0, f1, f2, f3, f4);

    for (int step = 0; step < 4; step++) {
        tower_mma<<<dim3(69, 2, 2), 256, SMEM_BYTES>>>(step, cls_b, box_b);
        gn_apply<<<dim3((NPIX * 64 + 255) / 256, 2), 256>>>(cls_gn_w, cls_gn_b,
                                                            box_gn_w, box_gn_b, step);
    }
    head_all<<<dim3(69, 2), 256, SMEM_BYTES>>>(score_b, pred_b, iou_b, scales, out);
}